// round 6
// baseline (speedup 1.0000x reference)
#include <cuda_runtime.h>
#include <cstdint>

#define BB 8
#define CC 256
#define NN 4096
#define GROUPS 32
#define CPG 8

// ---------------- scratch (device globals) --------------------------------
__device__ float g_h[(size_t)BB*NN*CC];    // groupnorm out, A-frag layout (token,channel)
__device__ float g_q[(size_t)BB*NN*CC];    // A-frag (token,channel)
__device__ float g_k[(size_t)BB*NN*CC];    // B-frag (token,channel)
__device__ float g_v[(size_t)BB*NN*CC];    // B-frag V layout (k=token)
__device__ float g_o[(size_t)BB*NN*CC];    // attention out, B-frag (token,channel)
__device__ float g_wq[CC*CC], g_wk[CC*CC], g_wv[CC*CC], g_wo[CC*CC];

// ---------------- helpers --------------------------------------------------
__device__ __forceinline__ float to_tf32(float x) {
    uint32_t u;
    asm("cvt.rna.tf32.f32 %0, %1;" : "=r"(u) : "f"(x));
    return __uint_as_float(u);
}

// D += A(16x8) * B(8x8); A,B tf32 bit-patterns in fp32 regs
#define MMA(c, a, b0, b1) \
    asm volatile("mma.sync.aligned.m16n8k8.row.col.f32.tf32.tf32.f32 " \
        "{%0,%1,%2,%3},{%4,%5,%6,%7},{%8,%9},{%0,%1,%2,%3};" \
        : "+f"((c)[0]), "+f"((c)[1]), "+f"((c)[2]), "+f"((c)[3]) \
        : "r"(__float_as_uint((a).x)), "r"(__float_as_uint((a).y)), \
          "r"(__float_as_uint((a).z)), "r"(__float_as_uint((a).w)), \
          "r"(__float_as_uint(b0)),  "r"(__float_as_uint(b1)))

// A-frag index over (m=n, k=c), k-extent 256: [n>>4][c>>3][lane][comp]
__device__ __forceinline__ size_t idxA(int n, int c) {
    int lane = ((n & 7) << 2) | (c & 3);
    int comp = (((c >> 2) & 1) << 1) | ((n >> 3) & 1);
    return ((((size_t)(n >> 4) * 32 + (c >> 3)) * 32 + lane) << 2) + comp;
}
// B-frag index over (n-dim=n, k=c), k-extent 256: [n>>3][c>>4][lane][comp]
__device__ __forceinline__ size_t idxB(int n, int c) {
    int lane = ((n & 7) << 2) | (c & 3);
    int comp = (((c >> 3) & 1) << 1) | ((c >> 2) & 1);
    return ((((size_t)(n >> 3) * 16 + (c >> 4)) * 32 + lane) << 2) + comp;
}
// V B-frag (k=token n, n-dim=channel c): [n>>4][c>>3][lane][comp]
__device__ __forceinline__ size_t idxV(int n, int c) {
    int lane = ((c & 7) << 2) | (n & 3);
    int comp = (((n >> 3) & 1) << 1) | ((n >> 2) & 1);
    return ((((size_t)(n >> 4) * 32 + (c >> 3)) * 32 + lane) << 2) + comp;
}

// ---------------- GroupNorm: writes h in A-frag layout ----------------------
__global__ __launch_bounds__(256) void gn_kernel(const float* __restrict__ x,
                                                 const float* __restrict__ gw,
                                                 const float* __restrict__ gb) {
    int b = blockIdx.x >> 5, g = blockIdx.x & 31, tid = threadIdx.x;
    const float4* x4 = (const float4*)(x + ((size_t)(b * CC + g * CPG)) * NN);
    float s = 0.f, ss = 0.f;
    for (int t = tid; t < 8192; t += 256) {
        float4 v = x4[t];
        s  += v.x + v.y + v.z + v.w;
        ss += v.x*v.x + v.y*v.y + v.z*v.z + v.w*v.w;
    }
    __shared__ float rs[8], rss[8];
    #pragma unroll
    for (int o = 16; o; o >>= 1) { s += __shfl_xor_sync(~0u, s, o); ss += __shfl_xor_sync(~0u, ss, o); }
    if ((tid & 31) == 0) { rs[tid >> 5] = s; rss[tid >> 5] = ss; }
    __syncthreads();
    if (tid < 32) {
        s = (tid < 8) ? rs[tid] : 0.f; ss = (tid < 8) ? rss[tid] : 0.f;
        #pragma unroll
        for (int o = 4; o; o >>= 1) { s += __shfl_xor_sync(~0u, s, o); ss += __shfl_xor_sync(~0u, ss, o); }
        if (tid == 0) { rs[0] = s; rss[0] = ss; }
    }
    __syncthreads();
    float mu = rs[0] * (1.f/32768.f);
    float var = rss[0] * (1.f/32768.f) - mu*mu;
    float rstd = rsqrtf(var + 1e-5f);
    float* hb = g_h + (size_t)b * NN * CC;
    #pragma unroll
    for (int c = 0; c < CPG; c++) {
        int ch = g * CPG + c;
        float A = rstd * gw[ch], Bc = gb[ch] - mu * A;
        for (int t = tid; t < 1024; t += 256) {
            float4 v = x4[c*1024 + t];
            int n = t * 4;
            hb[idxA(n + 0, ch)] = to_tf32(v.x*A + Bc);
            hb[idxA(n + 1, ch)] = to_tf32(v.y*A + Bc);
            hb[idxA(n + 2, ch)] = to_tf32(v.z*A + Bc);
            hb[idxA(n + 3, ch)] = to_tf32(v.w*A + Bc);
        }
    }
}

// ---------------- weight prep: frag-interleave the 4 weight matrices --------
__global__ __launch_bounds__(256) void wprep_kernel(const float* __restrict__ wq,
                                                    const float* __restrict__ wk,
                                                    const float* __restrict__ wv,
                                                    const float* __restrict__ wo) {
    int which = blockIdx.y;
    const float* src = (which == 0) ? wq : (which == 1) ? wk : (which == 2) ? wv : wo;
    float* dst = (which == 0) ? g_wq : (which == 1) ? g_wk : (which == 2) ? g_wv : g_wo;
    int e = blockIdx.x * 256 + threadIdx.x;  // over 65536
    int o = e >> 8, c = e & 255;
    float v = to_tf32(src[e]);
    dst[(which < 3) ? idxB(o, c) : idxA(o, c)] = v;
}

// ---------------- QKV projection via mma.sync (tf32) ------------------------
// q[n][o] = sum_c h[n][c]*W[o][c] + bias[o]. A = h-frag, B = W-frag.
// Grid (32, 2, 8), 256 thr, warps 4(m)x2(n), warp tile 32x64.
// MODE: 0=store Q A-frag, 1=store K B-frag, 2=store V V-frag.
template <int MODE>
__global__ __launch_bounds__(256) void projmma_kernel(const float* __restrict__ Wf,
                                                      const float* __restrict__ bias,
                                                      float* __restrict__ out) {
    extern __shared__ float sm[];
    float* Asm = sm;          // [ntile 8][ctile 8][128]
    float* Bsm = sm + 8192;   // [otile 16][ktile 4][128]
    int b = blockIdx.z, t0 = blockIdx.x * 128, o0 = blockIdx.y * 128;
    int tid = threadIdx.x, w = tid >> 5, lane = tid & 31;
    int wm = w >> 1, wn = w & 1;
    const float4* hsrc = (const float4*)(g_h + (size_t)b * NN * CC);
    const float4* wsrc = (const float4*)Wf;
    float acc[2][8][4] = {};

    for (int k0 = 0; k0 < CC; k0 += 64) {
        __syncthreads();
        #pragma unroll
        for (int i = 0; i < 8; i++) {
            int f = i * 256 + tid;
            int ntile = f >> 8, wi = f & 255;
            ((float4*)Asm)[ntile * 256 + wi] =
                hsrc[(((t0 >> 4) + ntile) * 32 + (k0 >> 3)) * 32 + wi];
            int otile = f >> 7, wj = f & 127;
            ((float4*)Bsm)[otile * 128 + wj] =
                wsrc[(((o0 >> 3) + otile) * 16 + (k0 >> 4)) * 32 + wj];
        }
        __syncthreads();
        #pragma unroll
        for (int kt = 0; kt < 4; kt++) {
            float4 Ae[2], Ao[2];
            #pragma unroll
            for (int mt = 0; mt < 2; mt++) {
                Ae[mt] = ((const float4*)Asm)[((2*wm+mt)*8 + 2*kt    ) * 32 + lane];
                Ao[mt] = ((const float4*)Asm)[((2*wm+mt)*8 + 2*kt + 1) * 32 + lane];
            }
            #pragma unroll
            for (int nt = 0; nt < 8; nt++) {
                float4 Bv = ((const float4*)Bsm)[((8*wn+nt)*4 + kt) * 32 + lane];
                #pragma unroll
                for (int mt = 0; mt < 2; mt++) {
                    MMA(acc[mt][nt], Ae[mt], Bv.x, Bv.y);
                    MMA(acc[mt][nt], Ao[mt], Bv.z, Bv.w);
                }
            }
        }
    }
    int r = lane >> 2, q = lane & 3;
    float* ob = out + (size_t)b * NN * CC;
    #pragma unroll
    for (int mt = 0; mt < 2; mt++)
        #pragma unroll
        for (int nt = 0; nt < 8; nt++)
            #pragma unroll
            for (int j = 0; j < 4; j++) {
                int n = t0 + (2*wm+mt)*16 + r + ((j >> 1) << 3);
                int c = o0 + (8*wn+nt)*8 + 2*q + (j & 1);
                float val = to_tf32(acc[mt][nt][j] + bias[c]);
                size_t idx = (MODE == 0) ? idxA(n, c) : (MODE == 1) ? idxB(n, c) : idxV(n, c);
                ob[idx] = val;
            }
}

// ---------------- mma.sync tf32 flash attention -----------------------------
// Grid (32, 8), 256 thr, 64-token KV tile, shared K/V phase buffer.
#define SM_FLOATS 57600

__global__ void __launch_bounds__(256, 1) attn_mma_kernel() {
    extern __shared__ float sm[];
    float* Qs  = sm;
    float* KVs = sm + 32768;
    float* Ps  = sm + 49152;
    float* Ls  = sm + 57344;

    int tid = threadIdx.x, w = tid >> 5, lane = tid & 31;
    int r = lane >> 2, q = lane & 3;
    int wm = w >> 1, wn = w & 1;   // QK: 4x2 warps, 32x32 tiles
    int wmP = w >> 2, wnP = w & 3; // PV: 2x4 warps, 64x64 tiles
    int b = blockIdx.y, qt = blockIdx.x;

    const float4* qg = (const float4*)(g_q + (size_t)b * NN * CC + (size_t)qt * 32768);
    #pragma unroll
    for (int i = 0; i < 32; i++) ((float4*)Qs)[i * 256 + tid] = qg[i * 256 + tid];

    const float* kg = g_k + (size_t)b * NN * CC;
    const float* vg = g_v + (size_t)b * NN * CC;

    float accO[4][8][4] = {};
    float lacc[2][2] = {};
    const float EMUL = 0.09016994374f;  // (1/16)*log2(e)

    for (int t = 0; t < 64; t++) {
        __syncthreads();
        const float4* ksrc = (const float4*)(kg + (size_t)t * 16384);
        #pragma unroll
        for (int i = 0; i < 16; i++) ((float4*)KVs)[i * 256 + tid] = ksrc[i * 256 + tid];
        __syncthreads();

        float p[2][4][4];
        {
            float s[2][4][4] = {};
            #pragma unroll
            for (int kp = 0; kp < 16; kp++) {
                float4 Ae[2], Ao[2];
                #pragma unroll
                for (int mt = 0; mt < 2; mt++) {
                    Ae[mt] = *(const float4*)(Qs + ((2*wm+mt)*32 + 2*kp    ) * 128 + lane * 4);
                    Ao[mt] = *(const float4*)(Qs + ((2*wm+mt)*32 + 2*kp + 1) * 128 + lane * 4);
                }
                #pragma unroll
                for (int nt = 0; nt < 4; nt++) {
                    float4 Bv = *(const float4*)(KVs + ((4*wn+nt)*16 + kp) * 128 + lane * 4);
                    #pragma unroll
                    for (int mt = 0; mt < 2; mt++) {
                        MMA(s[mt][nt], Ae[mt], Bv.x, Bv.y);
                        MMA(s[mt][nt], Ao[mt], Bv.z, Bv.w);
                    }
                }
            }
            #pragma unroll
            for (int mt = 0; mt < 2; mt++) {
                float rlo = 0.f, rhi = 0.f;
                #pragma unroll
                for (int nt = 0; nt < 4; nt++) {
                    p[mt][nt][0] = exp2f(s[mt][nt][0] * EMUL);
                    p[mt][nt][1] = exp2f(s[mt][nt][1] * EMUL);
                    p[mt][nt][2] = exp2f(s[mt][nt][2] * EMUL);
                    p[mt][nt][3] = exp2f(s[mt][nt][3] * EMUL);
                    rlo += p[mt][nt][0] + p[mt][nt][1];
                    rhi += p[mt][nt][2] + p[mt][nt][3];
                }
                rlo += __shfl_xor_sync(~0u, rlo, 1); rlo += __shfl_xor_sync(~0u, rlo, 2);
                rhi += __shfl_xor_sync(~0u, rhi, 1); rhi += __shfl_xor_sync(~0u, rhi, 2);
                lacc[mt][0] += rlo; lacc[mt][1] += rhi;
            }
            int c0l = r*4 + ((2*q)&3),   c0c = ((2*q)>>2)<<1;
            int c1l = r*4 + ((2*q+1)&3), c1c = ((2*q+1)>>2)<<1;
            #pragma unroll
            for (int mt = 0; mt < 2; mt++)
                #pragma unroll
                for (int nt = 0; nt < 4; nt++) {
                    int base = ((2*wm+mt)*8 + 4*wn+nt) * 128;
                    Ps[base + (c0l<<2) + c0c]     = to_tf32(p[mt][nt][0]);
                    Ps[base + (c1l<<2) + c1c]     = to_tf32(p[mt][nt][1]);
                    Ps[base + (c0l<<2) + c0c + 1] = to_tf32(p[mt][nt][2]);
                    Ps[base + (c1l<<2) + c1c + 1] = to_tf32(p[mt][nt][3]);
                }
        }
        __syncthreads();

        const float4* vsrc = (const float4*)(vg + (size_t)t * 16384);
        #pragma unroll
        for (int i = 0; i < 16; i++) ((float4*)KVs)[i * 256 + tid] = vsrc[i * 256 + tid];
        __syncthreads();

        #pragma unroll
        for (int kp = 0; kp < 4; kp++) {
            float4 Ae[4], Ao[4];
            #pragma unroll
            for (int mt = 0; mt < 4; mt++) {
                Ae[mt] = *(const float4*)(Ps + ((4*wmP+mt)*8 + 2*kp    ) * 128 + lane * 4);
                Ao[mt] = *(const float4*)(Ps + ((4*wmP+mt)*8 + 2*kp + 1) * 128 + lane * 4);
            }
            #pragma unroll
            for (int nt = 0; nt < 8; nt++) {
                float4 Bv = *(const float4*)(KVs + (kp*32 + 8*wnP + nt) * 128 + lane * 4);
                #pragma unroll
                for (int mt = 0; mt < 4; mt++) {
                    MMA(accO[mt][nt], Ae[mt], Bv.x, Bv.y);
                    MMA(accO[mt][nt], Ao[mt], Bv.z, Bv.w);
                }
            }
        }
    }

    if (q == 0) {
        #pragma unroll
        for (int mt = 0; mt < 2; mt++) {
            Ls[wn*128 + 32*wm + 16*mt + r]     = lacc[mt][0];
            Ls[wn*128 + 32*wm + 16*mt + r + 8] = lacc[mt][1];
        }
    }
    __syncthreads();

    // normalize + store o in B-frag layout (for oproj)
    float* og = g_o + (size_t)b * NN * CC;
    #pragma unroll
    for (int mt = 0; mt < 4; mt++) {
        int lr0 = 64*wmP + 16*mt + r, lr1 = lr0 + 8;
        float i0 = 1.f / (Ls[lr0] + Ls[128 + lr0]);
        float i1 = 1.f / (Ls[lr1] + Ls[128 + lr1]);
        #pragma unroll
        for (int nt = 0; nt < 8; nt++) {
            #pragma unroll
            for (int j = 0; j < 4; j++) {
                int n = qt*128 + ((j >> 1) ? lr1 : lr0);
                int c = 64*wnP + 8*nt + 2*q + (j & 1);
                float val = accO[mt][nt][j] * ((j >> 1) ? i1 : i0);
                og[idxB(n, c)] = to_tf32(val);
            }
        }
    }
}

// ---------------- Out projection via mma.sync --------------------------------
// out[b][c][n] = sum_k Wo[c][k]*o[n][k] + bo[c] + x[b][c][n]. A = Wo-frag, B = o-frag.
// Grid (32, 2, 8): x -> token n0, y -> channel c0. Warps 4(m=c)x2(n=token).
__global__ __launch_bounds__(256) void oprojmma_kernel(const float* __restrict__ bo,
                                                       const float* __restrict__ x,
                                                       float* __restrict__ out) {
    extern __shared__ float sm[];
    float* Asm = sm;          // Wo chunk: [ctile 8][ktile 8][128]
    float* Bsm = sm + 8192;   // o  chunk: [ntile 16][ktile 4][128]
    int b = blockIdx.z, n0 = blockIdx.x * 128, c0 = blockIdx.y * 128;
    int tid = threadIdx.x, w = tid >> 5, lane = tid & 31;
    int wm = w >> 1, wn = w & 1;
    const float4* asrc = (const float4*)g_wo;
    const float4* bsrc = (const float4*)(g_o + (size_t)b * NN * CC);
    float acc[2][8][4] = {};

    for (int k0 = 0; k0 < CC; k0 += 64) {
        __syncthreads();
        #pragma unroll
        for (int i = 0; i < 8; i++) {
            int f = i * 256 + tid;
            int ctile = f >> 8, wi = f & 255;
            ((float4*)Asm)[ctile * 256 + wi] =
                asrc[(((c0 >> 4) + ctile) * 32 + (k0 >> 3)) * 32 + wi];
            int ntile = f >> 7, wj = f & 127;
            ((float4*)Bsm)[ntile * 128 + wj] =
                bsrc[(((n0 >> 3) + ntile) * 16 + (k0 >> 4)) * 32 + wj];
        }
        __syncthreads();
        #pragma unroll
        for (int kt = 0; kt < 4; kt++) {
            float4 Ae[2], Ao[2];
            #pragma unroll
            for (int mt = 0; mt < 2; mt++) {
                Ae[mt] = ((const float4*)Asm)[((2*wm+mt)*8 + 2*kt    ) * 32 + lane];
                Ao[mt] = ((const float4*)Asm)[((2*wm+mt)*8 + 2*kt + 1) * 32 + lane];
            }
            #pragma unroll
            for (int nt = 0; nt < 8; nt++) {
                float4 Bv = ((const float4*)Bsm)[((8*wn+nt)*4 + kt) * 32 + lane];
                #pragma unroll
                for (int mt = 0; mt < 2; mt++) {
                    MMA(acc[mt][nt], Ae[mt], Bv.x, Bv.y);
                    MMA(acc[mt][nt], Ao[mt], Bv.z, Bv.w);
                }
            }
        }
    }
    int r = lane >> 2, q = lane & 3;
    #pragma unroll
    for (int mt = 0; mt < 2; mt++) {
        int c_ = c0 + (2*wm+mt)*16 + r;
        float b0v = bo[c_], b1v = bo[c_ + 8];
        #pragma unroll
        for (int nt = 0; nt < 8; nt++) {
            int n_ = n0 + (8*wn+nt)*8 + 2*q;
            size_t base0 = ((size_t)b * CC + c_) * NN + n_;
            size_t base1 = ((size_t)b * CC + c_ + 8) * NN + n_;
            float2 xv0 = *(const float2*)(x + base0);
            float2 xv1 = *(const float2*)(x + base1);
            float2 r0 = { acc[mt][nt][0] + b0v + xv0.x, acc[mt][nt][1] + b0v + xv0.y };
            float2 r1 = { acc[mt][nt][2] + b1v + xv1.x, acc[mt][nt][3] + b1v + xv1.y };
            *(float2*)(out + base0) = r0;
            *(float2*)(out + base1) = r1;
        }
    }
}

// ---------------- launch -----------------------------------------------------
extern "C" void kernel_launch(void* const* d_in, const int* in_sizes, int n_in,
                              void* d_out, int out_size) {
    const float* x    = (const float*)d_in[0];
    const float* gn_w = (const float*)d_in[1];
    const float* gn_b = (const float*)d_in[2];
    const float* wq   = (const float*)d_in[3];
    const float* bq   = (const float*)d_in[4];
    const float* wk   = (const float*)d_in[5];
    const float* bk   = (const float*)d_in[6];
    const float* wv   = (const float*)d_in[7];
    const float* bv   = (const float*)d_in[8];
    const float* wo   = (const float*)d_in[9];
    const float* bo   = (const float*)d_in[10];
    float* out = (float*)d_out;

    void* pq; cudaGetSymbolAddress(&pq, g_q);
    void* pk; cudaGetSymbolAddress(&pk, g_k);
    void* pv; cudaGetSymbolAddress(&pv, g_v);
    void* pwq; cudaGetSymbolAddress(&pwq, g_wq);
    void* pwk; cudaGetSymbolAddress(&pwk, g_wk);
    void* pwv; cudaGetSymbolAddress(&pwv, g_wv);

    static bool attr_done = false;
    if (!attr_done) {
        cudaFuncSetAttribute(attn_mma_kernel, cudaFuncAttributeMaxDynamicSharedMemorySize,
                             SM_FLOATS * (int)sizeof(float));
        cudaFuncSetAttribute(projmma_kernel<0>, cudaFuncAttributeMaxDynamicSharedMemorySize, 65536);
        cudaFuncSetAttribute(projmma_kernel<1>, cudaFuncAttributeMaxDynamicSharedMemorySize, 65536);
        cudaFuncSetAttribute(projmma_kernel<2>, cudaFuncAttributeMaxDynamicSharedMemorySize, 65536);
        cudaFuncSetAttribute(oprojmma_kernel,   cudaFuncAttributeMaxDynamicSharedMemorySize, 65536);
        attr_done = true;
    }

    gn_kernel<<<BB * GROUPS, 256>>>(x, gn_w, gn_b);
    wprep_kernel<<<dim3(256, 4), 256>>>(wq, wk, wv, wo);

    dim3 pgrid(NN / 128, CC / 128, BB);
    projmma_kernel<0><<<pgrid, 256, 65536>>>((const float*)pwq, bq, (float*)pq);
    projmma_kernel<1><<<pgrid, 256, 65536>>>((const float*)pwk, bk, (float*)pk);
    projmma_kernel<2><<<pgrid, 256, 65536>>>((const float*)pwv, bv, (float*)pv);

    attn_mma_kernel<<<dim3(32, BB), 256, SM_FLOATS * sizeof(float)>>>();

    oprojmma_kernel<<<pgrid, 256, 65536>>>(bo, x, out);
}

// round 7
// speedup vs baseline: 1.4744x; 1.4744x over previous
#include <cuda_runtime.h>
#include <cstdint>

#define BB 8
#define CC 256
#define NN 4096
#define GROUPS 32
#define CPG 8

// ---------------- scratch (device globals) --------------------------------
__device__ float g_h[(size_t)BB*NN*CC];    // groupnorm out, A-frag layout (token,channel)
__device__ float g_q[(size_t)BB*NN*CC];    // A-frag (token,channel)
__device__ float g_k[(size_t)BB*NN*CC];    // B-frag (token,channel)
__device__ float g_v[(size_t)BB*NN*CC];    // B-frag V layout (k=token)
__device__ float g_o[(size_t)BB*NN*CC];    // attention out, B-frag (token,channel)
__device__ float g_wq[CC*CC], g_wk[CC*CC], g_wv[CC*CC], g_wo[CC*CC];

// ---------------- helpers --------------------------------------------------
__device__ __forceinline__ float to_tf32(float x) {
    uint32_t u;
    asm("cvt.rna.tf32.f32 %0, %1;" : "=r"(u) : "f"(x));
    return __uint_as_float(u);
}

// D += A(16x8) * B(8x8); A,B tf32 bit-patterns in fp32 regs
#define MMA(c, a, b0, b1) \
    asm volatile("mma.sync.aligned.m16n8k8.row.col.f32.tf32.tf32.f32 " \
        "{%0,%1,%2,%3},{%4,%5,%6,%7},{%8,%9},{%0,%1,%2,%3};" \
        : "+f"((c)[0]), "+f"((c)[1]), "+f"((c)[2]), "+f"((c)[3]) \
        : "r"(__float_as_uint((a).x)), "r"(__float_as_uint((a).y)), \
          "r"(__float_as_uint((a).z)), "r"(__float_as_uint((a).w)), \
          "r"(__float_as_uint(b0)),  "r"(__float_as_uint(b1)))

// A-frag index over (m=n, k=c), k-extent 256: [n>>4][c>>3][lane][comp]
__device__ __forceinline__ size_t idxA(int n, int c) {
    int lane = ((n & 7) << 2) | (c & 3);
    int comp = (((c >> 2) & 1) << 1) | ((n >> 3) & 1);
    return ((((size_t)(n >> 4) * 32 + (c >> 3)) * 32 + lane) << 2) + comp;
}
// B-frag index over (n-dim=n, k=c), k-extent 256: [n>>3][c>>4][lane][comp]
__device__ __forceinline__ size_t idxB(int n, int c) {
    int lane = ((n & 7) << 2) | (c & 3);
    int comp = (((c >> 3) & 1) << 1) | ((c >> 2) & 1);
    return ((((size_t)(n >> 3) * 16 + (c >> 4)) * 32 + lane) << 2) + comp;
}
// V B-frag (k=token n, n-dim=channel c): [n>>4][c>>3][lane][comp]
__device__ __forceinline__ size_t idxV(int n, int c) {
    int lane = ((c & 7) << 2) | (n & 3);
    int comp = (((n >> 3) & 1) << 1) | ((n >> 2) & 1);
    return ((((size_t)(n >> 4) * 32 + (c >> 3)) * 32 + lane) << 2) + comp;
}

// ---------------- GroupNorm: A-frag output via smem stage (coalesced) -------
__global__ __launch_bounds__(256) void gn_kernel(const float* __restrict__ x,
                                                 const float* __restrict__ gw,
                                                 const float* __restrict__ gb) {
    int b = blockIdx.x >> 5, g = blockIdx.x & 31, tid = threadIdx.x;
    const float* xb = x + ((size_t)(b * CC + g * CPG)) * NN;
    const float4* x4 = (const float4*)xb;
    float s = 0.f, ss = 0.f;
    for (int t = tid; t < 8192; t += 256) {
        float4 v = x4[t];
        s  += v.x + v.y + v.z + v.w;
        ss += v.x*v.x + v.y*v.y + v.z*v.z + v.w*v.w;
    }
    __shared__ float rs[8], rss[8];
    __shared__ float stage[2048];
    #pragma unroll
    for (int o = 16; o; o >>= 1) { s += __shfl_xor_sync(~0u, s, o); ss += __shfl_xor_sync(~0u, ss, o); }
    if ((tid & 31) == 0) { rs[tid >> 5] = s; rss[tid >> 5] = ss; }
    __syncthreads();
    if (tid < 32) {
        s = (tid < 8) ? rs[tid] : 0.f; ss = (tid < 8) ? rss[tid] : 0.f;
        #pragma unroll
        for (int o = 4; o; o >>= 1) { s += __shfl_xor_sync(~0u, s, o); ss += __shfl_xor_sync(~0u, ss, o); }
        if (tid == 0) { rs[0] = s; rss[0] = ss; }
    }
    __syncthreads();
    float mu = rs[0] * (1.f/32768.f);
    float var = rss[0] * (1.f/32768.f) - mu*mu;
    float rstd = rsqrtf(var + 1e-5f);
    float Am[8], Bm[8];
    #pragma unroll
    for (int c = 0; c < 8; c++) {
        Am[c] = rstd * gw[g * CPG + c];
        Bm[c] = gb[g * CPG + c] - mu * Am[c];
    }
    float4* dst = (float4*)(g_h + (size_t)b * NN * CC);
    // 16 passes x 256 tokens: scatter to smem frag tiles, flush coalesced
    for (int pass = 0; pass < 16; pass++) {
        int n = pass * 256 + tid;
        int lbase = (tid >> 4) * 128;
        int lane_n = (tid & 7) << 2;
        int comp_n = (tid >> 3) & 1;
        #pragma unroll
        for (int c = 0; c < 8; c++) {
            float val = to_tf32(xb[(size_t)c * NN + n] * Am[c] + Bm[c]);
            stage[lbase + ((lane_n | (c & 3)) << 2) + ((((c >> 2) & 1) << 1) | comp_n)] = val;
        }
        __syncthreads();
        #pragma unroll
        for (int k = 0; k < 2; k++) {
            int f = k * 256 + tid;
            int i = f >> 5, w2 = f & 31;
            dst[((size_t)(pass * 16 + i) * 32 + g) * 32 + w2] = ((const float4*)stage)[i * 32 + w2];
        }
        __syncthreads();
    }
}

// ---------------- weight prep: frag-interleave the 4 weight matrices --------
__global__ __launch_bounds__(256) void wprep_kernel(const float* __restrict__ wq,
                                                    const float* __restrict__ wk,
                                                    const float* __restrict__ wv,
                                                    const float* __restrict__ wo) {
    int which = blockIdx.y;
    const float* src = (which == 0) ? wq : (which == 1) ? wk : (which == 2) ? wv : wo;
    float* dst = (which == 0) ? g_wq : (which == 1) ? g_wk : (which == 2) ? g_wv : g_wo;
    int e = blockIdx.x * 256 + threadIdx.x;  // over 65536
    int o = e >> 8, c = e & 255;
    float v = to_tf32(src[e]);
    dst[(which < 3) ? idxB(o, c) : idxA(o, c)] = v;
}

// ---------------- QKV projection via mma.sync (tf32) ------------------------
// MODE: 0=store Q A-frag, 1=store K B-frag, 2=store V V-frag.
template <int MODE>
__global__ __launch_bounds__(256) void projmma_kernel(const float* __restrict__ Wf,
                                                      const float* __restrict__ bias,
                                                      float* __restrict__ out) {
    extern __shared__ float sm[];
    float* Asm = sm;          // [ntile 8][ctile 8][128]
    float* Bsm = sm + 8192;   // [otile 16][ktile 4][128]
    int b = blockIdx.z, t0 = blockIdx.x * 128, o0 = blockIdx.y * 128;
    int tid = threadIdx.x, w = tid >> 5, lane = tid & 31;
    int wm = w >> 1, wn = w & 1;
    const float4* hsrc = (const float4*)(g_h + (size_t)b * NN * CC);
    const float4* wsrc = (const float4*)Wf;
    float acc[2][8][4] = {};

    for (int k0 = 0; k0 < CC; k0 += 64) {
        __syncthreads();
        #pragma unroll
        for (int i = 0; i < 8; i++) {
            int f = i * 256 + tid;
            int ntile = f >> 8, wi = f & 255;
            ((float4*)Asm)[ntile * 256 + wi] =
                hsrc[(((t0 >> 4) + ntile) * 32 + (k0 >> 3)) * 32 + wi];
            int otile = f >> 7, wj = f & 127;
            ((float4*)Bsm)[otile * 128 + wj] =
                wsrc[(((o0 >> 3) + otile) * 16 + (k0 >> 4)) * 32 + wj];
        }
        __syncthreads();
        #pragma unroll
        for (int kt = 0; kt < 4; kt++) {
            float4 Ae[2], Ao[2];
            #pragma unroll
            for (int mt = 0; mt < 2; mt++) {
                Ae[mt] = ((const float4*)Asm)[((2*wm+mt)*8 + 2*kt    ) * 32 + lane];
                Ao[mt] = ((const float4*)Asm)[((2*wm+mt)*8 + 2*kt + 1) * 32 + lane];
            }
            #pragma unroll
            for (int nt = 0; nt < 8; nt++) {
                float4 Bv = ((const float4*)Bsm)[((8*wn+nt)*4 + kt) * 32 + lane];
                #pragma unroll
                for (int mt = 0; mt < 2; mt++) {
                    MMA(acc[mt][nt], Ae[mt], Bv.x, Bv.y);
                    MMA(acc[mt][nt], Ao[mt], Bv.z, Bv.w);
                }
            }
        }
    }
    int r = lane >> 2, q = lane & 3;
    float* ob = out + (size_t)b * NN * CC;
    #pragma unroll
    for (int mt = 0; mt < 2; mt++)
        #pragma unroll
        for (int nt = 0; nt < 8; nt++)
            #pragma unroll
            for (int j = 0; j < 4; j++) {
                int n = t0 + (2*wm+mt)*16 + r + ((j >> 1) << 3);
                int c = o0 + (8*wn+nt)*8 + 2*q + (j & 1);
                float val = to_tf32(acc[mt][nt][j] + bias[c]);
                size_t idx = (MODE == 0) ? idxA(n, c) : (MODE == 1) ? idxB(n, c) : idxV(n, c);
                ob[idx] = val;
            }
}

// ---------------- mma.sync tf32 flash attention -----------------------------
// Grid (32, 8), 256 thr, 64-token KV tile, shared K/V phase buffer.
#define SM_FLOATS 57600

__global__ void __launch_bounds__(256, 1) attn_mma_kernel() {
    extern __shared__ float sm[];
    float* Qs  = sm;
    float* KVs = sm + 32768;
    float* Ps  = sm + 49152;
    float* Ls  = sm + 57344;

    int tid = threadIdx.x, w = tid >> 5, lane = tid & 31;
    int r = lane >> 2, q = lane & 3;
    int wm = w >> 1, wn = w & 1;   // QK: 4x2 warps, 32x32 tiles
    int wmP = w >> 2, wnP = w & 3; // PV: 2x4 warps, 64x64 tiles
    int b = blockIdx.y, qt = blockIdx.x;

    const float4* qg = (const float4*)(g_q + (size_t)b * NN * CC + (size_t)qt * 32768);
    #pragma unroll
    for (int i = 0; i < 32; i++) ((float4*)Qs)[i * 256 + tid] = qg[i * 256 + tid];

    const float* kg = g_k + (size_t)b * NN * CC;
    const float* vg = g_v + (size_t)b * NN * CC;

    float accO[4][8][4] = {};
    float lacc[2][2] = {};
    const float EMUL = 0.09016994374f;  // (1/16)*log2(e)

    for (int t = 0; t < 64; t++) {
        __syncthreads();
        const float4* ksrc = (const float4*)(kg + (size_t)t * 16384);
        #pragma unroll
        for (int i = 0; i < 16; i++) ((float4*)KVs)[i * 256 + tid] = ksrc[i * 256 + tid];
        __syncthreads();

        float p[2][4][4];
        {
            float s[2][4][4] = {};
            #pragma unroll
            for (int kp = 0; kp < 16; kp++) {
                float4 Ae[2], Ao[2];
                #pragma unroll
                for (int mt = 0; mt < 2; mt++) {
                    Ae[mt] = *(const float4*)(Qs + ((2*wm+mt)*32 + 2*kp    ) * 128 + lane * 4);
                    Ao[mt] = *(const float4*)(Qs + ((2*wm+mt)*32 + 2*kp + 1) * 128 + lane * 4);
                }
                #pragma unroll
                for (int nt = 0; nt < 4; nt++) {
                    float4 Bv = *(const float4*)(KVs + ((4*wn+nt)*16 + kp) * 128 + lane * 4);
                    #pragma unroll
                    for (int mt = 0; mt < 2; mt++) {
                        MMA(s[mt][nt], Ae[mt], Bv.x, Bv.y);
                        MMA(s[mt][nt], Ao[mt], Bv.z, Bv.w);
                    }
                }
            }
            #pragma unroll
            for (int mt = 0; mt < 2; mt++) {
                float rlo = 0.f, rhi = 0.f;
                #pragma unroll
                for (int nt = 0; nt < 4; nt++) {
                    p[mt][nt][0] = exp2f(s[mt][nt][0] * EMUL);
                    p[mt][nt][1] = exp2f(s[mt][nt][1] * EMUL);
                    p[mt][nt][2] = exp2f(s[mt][nt][2] * EMUL);
                    p[mt][nt][3] = exp2f(s[mt][nt][3] * EMUL);
                    rlo += p[mt][nt][0] + p[mt][nt][1];
                    rhi += p[mt][nt][2] + p[mt][nt][3];
                }
                rlo += __shfl_xor_sync(~0u, rlo, 1); rlo += __shfl_xor_sync(~0u, rlo, 2);
                rhi += __shfl_xor_sync(~0u, rhi, 1); rhi += __shfl_xor_sync(~0u, rhi, 2);
                lacc[mt][0] += rlo; lacc[mt][1] += rhi;
            }
            int c0l = r*4 + ((2*q)&3),   c0c = ((2*q)>>2)<<1;
            int c1l = r*4 + ((2*q+1)&3), c1c = ((2*q+1)>>2)<<1;
            #pragma unroll
            for (int mt = 0; mt < 2; mt++)
                #pragma unroll
                for (int nt = 0; nt < 4; nt++) {
                    int base = ((2*wm+mt)*8 + 4*wn+nt) * 128;
                    Ps[base + (c0l<<2) + c0c]     = to_tf32(p[mt][nt][0]);
                    Ps[base + (c1l<<2) + c1c]     = to_tf32(p[mt][nt][1]);
                    Ps[base + (c0l<<2) + c0c + 1] = to_tf32(p[mt][nt][2]);
                    Ps[base + (c1l<<2) + c1c + 1] = to_tf32(p[mt][nt][3]);
                }
        }
        __syncthreads();

        const float4* vsrc = (const float4*)(vg + (size_t)t * 16384);
        #pragma unroll
        for (int i = 0; i < 16; i++) ((float4*)KVs)[i * 256 + tid] = vsrc[i * 256 + tid];
        __syncthreads();

        #pragma unroll
        for (int kp = 0; kp < 4; kp++) {
            float4 Ae[4], Ao[4];
            #pragma unroll
            for (int mt = 0; mt < 4; mt++) {
                Ae[mt] = *(const float4*)(Ps + ((4*wmP+mt)*8 + 2*kp    ) * 128 + lane * 4);
                Ao[mt] = *(const float4*)(Ps + ((4*wmP+mt)*8 + 2*kp + 1) * 128 + lane * 4);
            }
            #pragma unroll
            for (int nt = 0; nt < 8; nt++) {
                float4 Bv = *(const float4*)(KVs + (kp*32 + 8*wnP + nt) * 128 + lane * 4);
                #pragma unroll
                for (int mt = 0; mt < 4; mt++) {
                    MMA(accO[mt][nt], Ae[mt], Bv.x, Bv.y);
                    MMA(accO[mt][nt], Ao[mt], Bv.z, Bv.w);
                }
            }
        }
    }

    if (q == 0) {
        #pragma unroll
        for (int mt = 0; mt < 2; mt++) {
            Ls[wn*128 + 32*wm + 16*mt + r]     = lacc[mt][0];
            Ls[wn*128 + 32*wm + 16*mt + r + 8] = lacc[mt][1];
        }
    }
    __syncthreads();

    // scatter normalized O into Qs (dead) in B-frag order, then coalesced copy
    #pragma unroll
    for (int mt = 0; mt < 4; mt++) {
        int lr0 = 64*wmP + 16*mt + r, lr1 = lr0 + 8;
        float i0 = 1.f / (Ls[lr0] + Ls[128 + lr0]);
        float i1 = 1.f / (Ls[lr1] + Ls[128 + lr1]);
        #pragma unroll
        for (int nt = 0; nt < 8; nt++) {
            #pragma unroll
            for (int j = 0; j < 4; j++) {
                int lr = (j >> 1) ? lr1 : lr0;
                int c = 64*wnP + 8*nt + 2*q + (j & 1);
                float val = accO[mt][nt][j] * ((j >> 1) ? i1 : i0);
                int lane2 = ((lr & 7) << 2) | (c & 3);
                int comp = (((c >> 3) & 1) << 1) | ((c >> 2) & 1);
                Qs[(((lr >> 3) * 16 + (c >> 4)) << 7) + (lane2 << 2) + comp] = to_tf32(val);
            }
        }
    }
    __syncthreads();
    float4* og4 = (float4*)(g_o + (size_t)b * NN * CC + (size_t)qt * 32768);
    #pragma unroll
    for (int i = 0; i < 32; i++) og4[i * 256 + tid] = ((const float4*)Qs)[i * 256 + tid];
}

// ---------------- Out projection via mma.sync --------------------------------
__global__ __launch_bounds__(256) void oprojmma_kernel(const float* __restrict__ bo,
                                                       const float* __restrict__ x,
                                                       float* __restrict__ out) {
    extern __shared__ float sm[];
    float* Asm = sm;          // Wo chunk: [ctile 8][ktile 8][128]
    float* Bsm = sm + 8192;   // o  chunk: [ntile 16][ktile 4][128]
    int b = blockIdx.z, n0 = blockIdx.x * 128, c0 = blockIdx.y * 128;
    int tid = threadIdx.x, w = tid >> 5, lane = tid & 31;
    int wm = w >> 1, wn = w & 1;
    const float4* asrc = (const float4*)g_wo;
    const float4* bsrc = (const float4*)(g_o + (size_t)b * NN * CC);
    float acc[2][8][4] = {};

    for (int k0 = 0; k0 < CC; k0 += 64) {
        __syncthreads();
        #pragma unroll
        for (int i = 0; i < 8; i++) {
            int f = i * 256 + tid;
            int ctile = f >> 8, wi = f & 255;
            ((float4*)Asm)[ctile * 256 + wi] =
                asrc[(((c0 >> 4) + ctile) * 32 + (k0 >> 3)) * 32 + wi];
            int ntile = f >> 7, wj = f & 127;
            ((float4*)Bsm)[ntile * 128 + wj] =
                bsrc[(((n0 >> 3) + ntile) * 16 + (k0 >> 4)) * 32 + wj];
        }
        __syncthreads();
        #pragma unroll
        for (int kt = 0; kt < 4; kt++) {
            float4 Ae[2], Ao[2];
            #pragma unroll
            for (int mt = 0; mt < 2; mt++) {
                Ae[mt] = ((const float4*)Asm)[((2*wm+mt)*8 + 2*kt    ) * 32 + lane];
                Ao[mt] = ((const float4*)Asm)[((2*wm+mt)*8 + 2*kt + 1) * 32 + lane];
            }
            #pragma unroll
            for (int nt = 0; nt < 8; nt++) {
                float4 Bv = ((const float4*)Bsm)[((8*wn+nt)*4 + kt) * 32 + lane];
                #pragma unroll
                for (int mt = 0; mt < 2; mt++) {
                    MMA(acc[mt][nt], Ae[mt], Bv.x, Bv.y);
                    MMA(acc[mt][nt], Ao[mt], Bv.z, Bv.w);
                }
            }
        }
    }
    int r = lane >> 2, q = lane & 3;
    #pragma unroll
    for (int mt = 0; mt < 2; mt++) {
        int c_ = c0 + (2*wm+mt)*16 + r;
        float b0v = bo[c_], b1v = bo[c_ + 8];
        #pragma unroll
        for (int nt = 0; nt < 8; nt++) {
            int n_ = n0 + (8*wn+nt)*8 + 2*q;
            size_t base0 = ((size_t)b * CC + c_) * NN + n_;
            size_t base1 = ((size_t)b * CC + c_ + 8) * NN + n_;
            float2 xv0 = *(const float2*)(x + base0);
            float2 xv1 = *(const float2*)(x + base1);
            float2 r0 = { acc[mt][nt][0] + b0v + xv0.x, acc[mt][nt][1] + b0v + xv0.y };
            float2 r1 = { acc[mt][nt][2] + b1v + xv1.x, acc[mt][nt][3] + b1v + xv1.y };
            *(float2*)(out + base0) = r0;
            *(float2*)(out + base1) = r1;
        }
    }
}

// ---------------- launch -----------------------------------------------------
extern "C" void kernel_launch(void* const* d_in, const int* in_sizes, int n_in,
                              void* d_out, int out_size) {
    const float* x    = (const float*)d_in[0];
    const float* gn_w = (const float*)d_in[1];
    const float* gn_b = (const float*)d_in[2];
    const float* wq   = (const float*)d_in[3];
    const float* bq   = (const float*)d_in[4];
    const float* wk   = (const float*)d_in[5];
    const float* bk   = (const float*)d_in[6];
    const float* wv   = (const float*)d_in[7];
    const float* bv   = (const float*)d_in[8];
    const float* wo   = (const float*)d_in[9];
    const float* bo   = (const float*)d_in[10];
    float* out = (float*)d_out;

    void* pq; cudaGetSymbolAddress(&pq, g_q);
    void* pk; cudaGetSymbolAddress(&pk, g_k);
    void* pv; cudaGetSymbolAddress(&pv, g_v);
    void* pwq; cudaGetSymbolAddress(&pwq, g_wq);
    void* pwk; cudaGetSymbolAddress(&pwk, g_wk);
    void* pwv; cudaGetSymbolAddress(&pwv, g_wv);

    static bool attr_done = false;
    if (!attr_done) {
        cudaFuncSetAttribute(attn_mma_kernel, cudaFuncAttributeMaxDynamicSharedMemorySize,
                             SM_FLOATS * (int)sizeof(float));
        cudaFuncSetAttribute(projmma_kernel<0>, cudaFuncAttributeMaxDynamicSharedMemorySize, 65536);
        cudaFuncSetAttribute(projmma_kernel<1>, cudaFuncAttributeMaxDynamicSharedMemorySize, 65536);
        cudaFuncSetAttribute(projmma_kernel<2>, cudaFuncAttributeMaxDynamicSharedMemorySize, 65536);
        cudaFuncSetAttribute(oprojmma_kernel,   cudaFuncAttributeMaxDynamicSharedMemorySize, 65536);
        attr_done = true;
    }

    gn_kernel<<<BB * GROUPS, 256>>>(x, gn_w, gn_b);
    wprep_kernel<<<dim3(256, 4), 256>>>(wq, wk, wv, wo);

    dim3 pgrid(NN / 128, CC / 128, BB);
    projmma_kernel<0><<<pgrid, 256, 65536>>>((const float*)pwq, bq, (float*)pq);
    projmma_kernel<1><<<pgrid, 256, 65536>>>((const float*)pwk, bk, (float*)pk);
    projmma_kernel<2><<<pgrid, 256, 65536>>>((const float*)pwv, bv, (float*)pv);

    attn_mma_kernel<<<dim3(32, BB), 256, SM_FLOATS * sizeof(float)>>>();

    oprojmma_kernel<<<pgrid, 256, 65536>>>(bo, x, out);
}